// round 9
// baseline (speedup 1.0000x reference)
#include <cuda_runtime.h>
#include <cstdint>

// ExtractPatch: B=8, H=W=1024, N=4096 matches, R=8 -> 17x17 patches.
// out[bn][k]        = normalize(img1[b, my1 + k%17 - 8, mx1 + k/17 - 8])   k in [0,289)
// out[bn][289 + k]  = normalize(img2[b, my2 + k%17 - 8, mx2 + k/17 - 8])
// normalize: (p - mean) / (std_ddof1 + 1e-4), zero-padded outside image.

#define D      17
#define PATCH  289
#define HW     1024
#define NMATCH 4096
#define BATCH  8
#define WPB    4              // warps per block, one match per warp
#define THREADS (WPB * 32)
#define RS     20             // smem words per patch row (5 float4)
#define IMGW   (D * RS)       // 340 words per image buffer

__device__ __forceinline__ uint64_t pack2(float lo, float hi) {
    uint64_t r;
    asm("mov.b64 %0, {%1, %2};" : "=l"(r) : "f"(lo), "f"(hi));
    return r;
}
__device__ __forceinline__ void unpack2(uint64_t v, float& lo, float& hi) {
    asm("mov.b64 {%0, %1}, %2;" : "=f"(lo), "=f"(hi) : "l"(v));
}
__device__ __forceinline__ uint64_t add2(uint64_t a, uint64_t b) {
    uint64_t r;
    asm("add.rn.f32x2 %0, %1, %2;" : "=l"(r) : "l"(a), "l"(b));
    return r;
}
__device__ __forceinline__ uint64_t fma2(uint64_t a, uint64_t b, uint64_t c) {
    uint64_t r;
    asm("fma.rn.f32x2 %0, %1, %2, %3;" : "=l"(r) : "l"(a), "l"(b), "l"(c));
    return r;
}
__device__ __forceinline__ uint64_t shfl_xor2(uint64_t v, int mask) {
    uint32_t lo = (uint32_t)v, hi = (uint32_t)(v >> 32);
    lo = __shfl_xor_sync(0xffffffffu, lo, mask);
    hi = __shfl_xor_sync(0xffffffffu, hi, mask);
    return (uint64_t)lo | ((uint64_t)hi << 32);
}
__device__ __forceinline__ uint32_t smem_u32(const void* p) {
    return (uint32_t)__cvta_generic_to_shared(p);
}
// 16B global->shared, L2-only path (bypasses L1), own completion queue.
__device__ __forceinline__ void cp_async16(uint32_t dst, const void* src) {
    asm volatile("cp.async.cg.shared.global [%0], [%1], 16;" :: "r"(dst), "l"(src));
}
__device__ __forceinline__ void cp_async_commit_wait() {
    asm volatile("cp.async.commit_group;" ::: "memory");
    asm volatile("cp.async.wait_group 0;" ::: "memory");
}

__global__ __launch_bounds__(THREADS, 12)
void extract_patch_kernel(const float* __restrict__ img1,
                          const float* __restrict__ img2,
                          const int*   __restrict__ matches,
                          float*       __restrict__ out)
{
    // Per-warp row-major patch buffers: 17 rows x 20 words, both images.
    __shared__ __align__(16) float T[WPB][2 * IMGW];

    const int warpId = threadIdx.x >> 5;
    const int lane   = threadIdx.x & 31;

    const int bn = blockIdx.x * WPB + warpId;     // 0 .. 32767
    const int b  = bn >> 12;                      // NMATCH = 4096

    const float* __restrict__ ib1 = img1 + (size_t)b * (HW * HW);
    const float* __restrict__ ib2 = img2 + (size_t)b * (HW * HW);

    const int4 m = __ldg((const int4*)(matches + bn * 4));   // mx1, my1, mx2, my2

    float* __restrict__ Tw = T[warpId];
    const uint32_t TwS = smem_u32(Tw);

    uint64_t S = 0, Q = 0;   // packed (s1,s2), (q1,q2)
    int off1 = 0, off2 = 0;  // patch col 0 offset within the 20-word row window

    const bool interior =
        ((unsigned)(m.x - 8) <= (HW - D)) & ((unsigned)(m.y - 8) <= (HW - D)) &
        ((unsigned)(m.z - 8) <= (HW - D)) & ((unsigned)(m.w - 8) <= (HW - D));

    // lane -> slots s = it*32+lane (row = s/5, qi = s%5), valid s < 85
    int rowv[3], qiv[3];
    bool prv[3];
    #pragma unroll
    for (int it = 0; it < 3; ++it) {
        const int s = it * 32 + lane;
        rowv[it] = s / 5;
        qiv[it]  = s - rowv[it] * 5;
        prv[it]  = (s < 85);
    }

    if (interior) {
        const int x1 = m.x - 8, ya = m.y - 8;
        const int x2 = m.z - 8, yb = m.w - 8;
        off1 = x1 & 3;
        off2 = x2 & 3;
        const float4* rb1 = (const float4*)(ib1 + (size_t)ya * HW) + (x1 >> 2);
        const float4* rb2 = (const float4*)(ib2 + (size_t)yb * HW) + (x2 >> 2);

        // ---- gather: 6 LDGSTS.16 per thread-slot set, straight to smem ----
        #pragma unroll
        for (int it = 0; it < 3; ++it)
            if (prv[it])
                cp_async16(TwS + (uint32_t)((it * 32 + lane) * 16),
                           rb1 + rowv[it] * (HW / 4) + qiv[it]);
        #pragma unroll
        for (int it = 0; it < 3; ++it)
            if (prv[it])
                cp_async16(TwS + (uint32_t)(IMGW * 4 + (it * 32 + lane) * 16),
                           rb2 + rowv[it] * (HW / 4) + qiv[it]);
        cp_async_commit_wait();
        __syncwarp();

        // ---- sum phase: contiguous float4 reads (word 4s == row*20 + qi*4) ----
        #pragma unroll
        for (int it = 0; it < 3; ++it) {
            if (!prv[it]) continue;
            const float4 va = ((const float4*)Tw)[it * 32 + lane];
            const float4 vb = ((const float4*)(Tw + IMGW))[it * 32 + lane];
            const int base = 4 * qiv[it];
            const float* e1 = (const float*)&va;
            const float* e2 = (const float*)&vb;
            #pragma unroll
            for (int e = 0; e < 4; ++e) {
                const bool ok1 = (unsigned)(base + e - off1) < D;
                const bool ok2 = (unsigned)(base + e - off2) < D;
                const uint64_t u = pack2(ok1 ? e1[e] : 0.f, ok2 ? e2[e] : 0.f);
                S = add2(S, u);
                Q = fma2(u, u, Q);
            }
        }
    } else {
        // ---- slow path: scalar bounds-checked loads, off = 0 layout ----
        const int x1 = m.x - 8, y1 = m.y - 8;
        const int x2 = m.z - 8, y2 = m.w - 8;
        int c = (lane >= D) ? (lane - D) : lane;
        int r = (lane >= D) ? 1 : 0;
        #pragma unroll
        for (int t = 0; t < 10; ++t) {
            if (t < 9 || lane == 0) {
                const int yy1 = y1 + r, xx1 = x1 + c;
                const int yy2 = y2 + r, xx2 = x2 + c;
                float v1 = 0.f, v2 = 0.f;
                if (((unsigned)yy1 < HW) & ((unsigned)xx1 < HW))
                    v1 = __ldg(ib1 + yy1 * HW + xx1);
                if (((unsigned)yy2 < HW) & ((unsigned)xx2 < HW))
                    v2 = __ldg(ib2 + yy2 * HW + xx2);
                Tw[r * RS + c]        = v1;
                Tw[IMGW + r * RS + c] = v2;
                const uint64_t v = pack2(v1, v2);
                S = add2(S, v);
                Q = fma2(v, v, Q);
            }
            c += 15; r += 1;
            if (c >= D) { c -= D; r += 1; }
        }
        __syncwarp();
    }

    // ---- packed warp reduction ----
    #pragma unroll
    for (int o = 16; o > 0; o >>= 1) {
        S = add2(S, shfl_xor2(S, o));
        Q = add2(Q, shfl_xor2(Q, o));
    }
    float s1, s2, q1, q2;
    unpack2(S, s1, s2);
    unpack2(Q, q1, q2);

    const float mean1 = s1 * (1.0f / PATCH);
    const float mean2 = s2 * (1.0f / PATCH);
    float var1 = fmaxf((q1 - (float)PATCH * mean1 * mean1) * (1.0f / (PATCH - 1)), 0.f);
    float var2 = fmaxf((q2 - (float)PATCH * mean2 * mean2) * (1.0f / (PATCH - 1)), 0.f);
    const float inv1 = 1.0f / (sqrtf(var1) + 1e-4f);
    const float inv2 = 1.0f / (sqrtf(var2) + 1e-4f);
    const float bb1  = -mean1 * inv1;   // (v - m)*i = v*i + (-m*i)
    const float bb2  = -mean2 * inv2;

    // ---- transposed normalize + write: 578 scalar elems, 19 iters ----
    float* __restrict__ ob = out + (size_t)bn * (2 * PATCH);
    #pragma unroll
    for (int j = 0; j < 19; ++j) {
        const int idx = j * 32 + lane;            // 0 .. 577
        if (j < 18 || lane < 2) {
            const bool w2 = (idx >= PATCH);
            const int  k  = w2 ? (idx - PATCH) : idx;
            const int  c  = k / D;                // magic-mul by compiler
            const int  r  = k - c * D;
            const int  word = (w2 ? (IMGW + off2) : off1) + r * RS + c;
            const float v   = Tw[word];
            const float iv  = w2 ? inv2 : inv1;
            const float bb  = w2 ? bb2  : bb1;
            __stcs(ob + idx, fmaf(v, iv, bb));
        }
    }
}

extern "C" void kernel_launch(void* const* d_in, const int* in_sizes, int n_in,
                              void* d_out, int out_size)
{
    const float* img1    = (const float*)d_in[0];
    const float* img2    = (const float*)d_in[1];
    const int*   matches = (const int*)d_in[2];
    float*       out     = (float*)d_out;

    const int total_matches = BATCH * NMATCH;           // 32768
    const int blocks = total_matches / WPB;             // 8192

    extract_patch_kernel<<<blocks, THREADS>>>(img1, img2, matches, out);
}